// round 5
// baseline (speedup 1.0000x reference)
#include <cuda_runtime.h>
#include <cuda_fp16.h>
#include <stdint.h>

#define U_NODES 100000
#define I_NODES 50000
#define N_NODES 150000
#define H 64
#define UH (U_NODES * H)       // 6,400,000
#define IH (I_NODES * H)       // 3,200,000
#define NH (N_NODES * H)       // 9,600,000
#define E_IN 2000000
#define E_DIR 4000000
#define N_LAYERS 4

#define SCAN_BLK 1024
#define N_SCAN_BLOCKS ((N_NODES + SCAN_BLK - 1) / SCAN_BLK)   // 147

// ---------------- scratch (device globals; no runtime allocation) ------------
__device__ __align__(16) float d_deg[N_NODES];
__device__ __align__(16) float d_dinv[N_NODES];
__device__ __align__(16) int   d_cnt[N_NODES];
__device__ __align__(16) int   d_rowptr[N_NODES + 1];
__device__ __align__(16) int   d_wp[N_NODES];
__device__ __align__(16) int   d_partials[N_SCAN_BLOCKS];
__device__ __align__(16) int2  d_cw[E_DIR];          // packed (col, w bits)
__device__ __align__(16) __half d_e0[NH];            // fp16 input embeddings
__device__ __align__(16) __half d_L[N_LAYERS][NH];   // fp16 layer outputs
__device__ int d_is64;

// ---------------- dtype-robust index read ------------------------------------
// JAX default config downcasts int64 -> int32; edge arrays may be either.
__global__ void detect_kernel(const void* __restrict__ p) {
    if (blockIdx.x == 0 && threadIdx.x == 0) {
        const long long* q = (const long long*)p;
        int is64 = 1;
        for (int i = 0; i < 256; i++) {
            long long v = q[i];
            if (v < 0 || v >= N_NODES) { is64 = 0; break; }
        }
        d_is64 = is64;
    }
}

__device__ __forceinline__ int get_idx(const void* __restrict__ p, int k) {
    if (d_is64) return (int)((const long long*)p)[k];
    return ((const int*)p)[k];
}

// ---------------- build phase -------------------------------------------------

__global__ void zero_kernel() {
    int i = blockIdx.x * blockDim.x + threadIdx.x;
    if (i < N_NODES) { d_deg[i] = 0.0f; d_cnt[i] = 0; }
}

__global__ void deg_kernel(const void* __restrict__ eu,
                           const void* __restrict__ ei,
                           const float* __restrict__ ev) {
    int k = blockIdx.x * blockDim.x + threadIdx.x;
    if (k >= E_IN) return;
    int u  = get_idx(eu, k);
    int it = get_idx(ei, k);
    if ((unsigned)u >= U_NODES || (unsigned)it >= I_NODES) return;  // safety
    it += U_NODES;
    float v = ev[k];
    atomicAdd(&d_deg[u], v);
    atomicAdd(&d_deg[it], v);
    atomicAdd(&d_cnt[u], 1);
    atomicAdd(&d_cnt[it], 1);
}

__global__ void dinv_kernel() {
    int i = blockIdx.x * blockDim.x + threadIdx.x;
    if (i >= N_NODES) return;
    float dg = d_deg[i];
    d_dinv[i] = (dg > 0.0f) ? rsqrtf(fmaxf(dg, 1e-12f)) : 0.0f;
}

__global__ void scan1_kernel() {
    __shared__ int sh[SCAN_BLK];
    int t = threadIdx.x;
    int idx = blockIdx.x * SCAN_BLK + t;
    int v = (idx < N_NODES) ? d_cnt[idx] : 0;
    sh[t] = v;
    __syncthreads();
    for (int off = 1; off < SCAN_BLK; off <<= 1) {
        int x = (t >= off) ? sh[t - off] : 0;
        __syncthreads();
        sh[t] += x;
        __syncthreads();
    }
    if (idx < N_NODES) d_rowptr[idx] = sh[t] - v;   // block-local exclusive
    if (t == SCAN_BLK - 1) d_partials[blockIdx.x] = sh[t];
}

__global__ void scan2_kernel() {
    if (blockIdx.x == 0 && threadIdx.x == 0) {
        int s = 0;
        for (int i = 0; i < N_SCAN_BLOCKS; i++) {
            int v = d_partials[i];
            d_partials[i] = s;
            s += v;
        }
    }
}

__global__ void scan3_kernel() {
    int idx = blockIdx.x * blockDim.x + threadIdx.x;
    if (idx < N_NODES) {
        int rp = d_rowptr[idx] + d_partials[idx >> 10];
        d_rowptr[idx] = rp;
        d_wp[idx] = rp;
    }
    if (idx == 0) d_rowptr[N_NODES] = E_DIR;
}

__global__ void scatter_kernel(const void* __restrict__ eu,
                               const void* __restrict__ ei,
                               const float* __restrict__ ev) {
    int k = blockIdx.x * blockDim.x + threadIdx.x;
    if (k >= E_IN) return;
    int u  = get_idx(eu, k);
    int it = get_idx(ei, k);
    if ((unsigned)u >= U_NODES || (unsigned)it >= I_NODES) return;  // safety
    it += U_NODES;
    float v = ev[k];
    float w = d_dinv[u] * v * d_dinv[it];   // symmetric weight
    int wb = __float_as_int(w);
    int p0 = atomicAdd(&d_wp[u], 1);
    d_cw[p0] = make_int2(it, wb);
    int p1 = atomicAdd(&d_wp[it], 1);
    d_cw[p1] = make_int2(u, wb);
}

// e0 = fp16(concat(emb_users, emb_items))
__global__ void init_e_kernel(const float* __restrict__ emb_u,
                              const float* __restrict__ emb_i) {
    int i = blockIdx.x * blockDim.x + threadIdx.x;
    if (i >= NH) return;
    float v = (i < UH) ? emb_u[i] : emb_i[i - UH];
    d_e0[i] = __float2half(v);
}

// ---------------- propagation layers ------------------------------------------
// One warp per destination row. fp16 rows are 128 B. Lanes 0-15 handle the even
// edge of each pair, lanes 16-31 the odd edge; each lane loads 8 B (4 dims).
// fp32 accumulate; shfl_xor(16) combines the two edge-streams at the end.

#define GATHER(OFF)                                                           \
    {                                                                         \
        int2 cw = d_cw[j + (OFF) + hid];                                      \
        float w = __int_as_float(cw.y);                                       \
        const uint2* rp = (const uint2*)(ein + (size_t)cw.x * H);             \
        uint2 pv = rp[m];                                                     \
        float2 f0 = __half22float2(*(__half2*)&pv.x);                         \
        float2 f1 = __half22float2(*(__half2*)&pv.y);                         \
        sum.x += w * f0.x; sum.y += w * f0.y;                                 \
        sum.z += w * f1.x; sum.w += w * f1.y;                                 \
    }

__global__ void layer_kernel(int layer) {
    const __half* __restrict__ ein  = (layer == 0) ? d_e0 : d_L[layer - 1];
    __half*       __restrict__ eout = d_L[layer];
    int warp = (blockIdx.x * blockDim.x + threadIdx.x) >> 5;
    if (warp >= N_NODES) return;
    int lane = threadIdx.x & 31;
    int hid  = lane >> 4;     // 0: even edges, 1: odd edges
    int m    = lane & 15;     // 8-byte chunk within the 128 B row
    int s = d_rowptr[warp];
    int e = d_rowptr[warp + 1];
    float4 sum = make_float4(0.0f, 0.0f, 0.0f, 0.0f);
    int j = s;
    for (; j + 7 < e; j += 8) { GATHER(0) GATHER(2) GATHER(4) GATHER(6) }
    for (; j + 1 < e; j += 2) { GATHER(0) }
    if (j < e && hid == 0) {   // odd tail edge: only the even half processes it
        int2 cw = d_cw[j];
        float w = __int_as_float(cw.y);
        const uint2* rp = (const uint2*)(ein + (size_t)cw.x * H);
        uint2 pv = rp[m];
        float2 f0 = __half22float2(*(__half2*)&pv.x);
        float2 f1 = __half22float2(*(__half2*)&pv.y);
        sum.x += w * f0.x; sum.y += w * f0.y;
        sum.z += w * f1.x; sum.w += w * f1.y;
    }
    sum.x += __shfl_xor_sync(0xffffffffu, sum.x, 16);
    sum.y += __shfl_xor_sync(0xffffffffu, sum.y, 16);
    sum.z += __shfl_xor_sync(0xffffffffu, sum.z, 16);
    sum.w += __shfl_xor_sync(0xffffffffu, sum.w, 16);
    if (hid == 0) {
        __half2 o0 = __floats2half2_rn(sum.x, sum.y);
        __half2 o1 = __floats2half2_rn(sum.z, sum.w);
        uint2 pv;
        pv.x = *(unsigned int*)&o0;
        pv.y = *(unsigned int*)&o1;
        ((uint2*)(eout + (size_t)warp * H))[m] = pv;
    }
}

// ---------------- epilogue -----------------------------------------------------
// out = [(emb_u + sum_L)/25 | emb_u | (emb_i + sum_L)/25 | emb_i]
__global__ void final_kernel(const float* __restrict__ emb_u,
                             const float* __restrict__ emb_i,
                             float* __restrict__ out, int out_n) {
    const float sc = 1.0f / 25.0f;   // alpha * 1/(L+1) = 1/5 * 1/5
    int i = blockIdx.x * blockDim.x + threadIdx.x;
    if (i >= out_n) return;
    float v;
    if (i < UH) {
        float a = emb_u[i];
        a += __half2float(d_L[0][i]) + __half2float(d_L[1][i])
           + __half2float(d_L[2][i]) + __half2float(d_L[3][i]);
        v = a * sc;
    } else if (i < 2 * UH) {
        v = emb_u[i - UH];
    } else if (i < 2 * UH + IH) {
        int idx = UH + (i - 2 * UH);
        float a = emb_i[i - 2 * UH];
        a += __half2float(d_L[0][idx]) + __half2float(d_L[1][idx])
           + __half2float(d_L[2][idx]) + __half2float(d_L[3][idx]);
        v = a * sc;
    } else if (i < 2 * UH + 2 * IH) {
        v = emb_i[i - 2 * UH - IH];
    } else {
        v = 0.0f;
    }
    out[i] = v;
}

// ---------------- launch ------------------------------------------------------

extern "C" void kernel_launch(void* const* d_in, const int* in_sizes, int n_in,
                              void* d_out, int out_size) {
    const float* emb_u = (const float*)d_in[0];
    const float* emb_i = (const float*)d_in[1];
    const void*  eu    = d_in[2];
    const void*  ei    = d_in[3];
    const float* ev    = (const float*)d_in[4];
    float* out = (float*)d_out;

    const int TB = 256;
    int gb_nodes = (N_NODES + TB - 1) / TB;
    int gb_edges = (E_IN + TB - 1) / TB;
    int gb_nh    = (NH + TB - 1) / TB;
    int gb_out   = (out_size + TB - 1) / TB;

    detect_kernel<<<1, 32>>>(eu);
    zero_kernel<<<gb_nodes, TB>>>();
    deg_kernel<<<gb_edges, TB>>>(eu, ei, ev);
    dinv_kernel<<<gb_nodes, TB>>>();
    scan1_kernel<<<N_SCAN_BLOCKS, SCAN_BLK>>>();
    scan2_kernel<<<1, 32>>>();
    scan3_kernel<<<gb_nodes, TB>>>();
    scatter_kernel<<<gb_edges, TB>>>(eu, ei, ev);
    init_e_kernel<<<gb_nh, TB>>>(emb_u, emb_i);

    int layer_blocks = (N_NODES * 32 + TB - 1) / TB;   // warp per row
    layer_kernel<<<layer_blocks, TB>>>(0);
    layer_kernel<<<layer_blocks, TB>>>(1);
    layer_kernel<<<layer_blocks, TB>>>(2);
    layer_kernel<<<layer_blocks, TB>>>(3);

    final_kernel<<<gb_out, TB>>>(emb_u, emb_i, out, out_size);
}